// round 16
// baseline (speedup 1.0000x reference)
#include <cuda_runtime.h>
#include <cuda_bf16.h>

// CliffordLayerNorm — R16: 4 lanes per MV (last untested structural axis).
// Warp covers ONE group of 8 MVs (8KB); butterfly shrinks from 3 to 2
// serial shuffle stages and shuffle work per byte drops 2.8x (42/4KB ->
// 30/8KB). Everything else keeps the converged R13 configuration:
// 256-thread CTAs, occ 3, no loop, pass-2 global reload, plain stores.
//
// Element mapping within an MV (index bits 0..7):
//   j   = bits 0,1   (float4 component)        popc 0..2
//   sub = bits 2,3   (lane & 3)                p = popc(sub) in 0..2
//   k   = bits 4..7  (in-thread float4 index)  popc 0..4
// In-thread relative grade t = popc(k)+popc(j) in 0..6 (7 slots);
// butterfly over lane bits 0,1 merges 7 -> 8 -> 9 absolute grade sums.

#define NG 9
#define CEPS 1e-5f

__global__ void __launch_bounds__(256, 3)
clifford_ln_kernel(const float* __restrict__ x,
                   const float* __restrict__ weight,
                   const float* __restrict__ bias,
                   float* __restrict__ out,
                   int num_groups)   // groups of 2048 floats (8 MVs)
{
    const int lane = threadIdx.x & 31;
    const int grp = blockIdx.x * (blockDim.x >> 5) + (threadIdx.x >> 5);
    if (grp >= num_groups) return;

    const int sub = lane & 3;     // covers element bits 2,3
    const int mv  = lane >> 2;    // which of 8 MVs in the group
    const int p   = __popc(sub);  // relative grade base, 0..2

    // per-grade reciprocal counts C(8,g) = 1,8,28,56,70,56,28,8,1
    const float rc[NG] = {1.0f, 1.0f/8.0f, 1.0f/28.0f, 1.0f/56.0f, 1.0f/70.0f,
                          1.0f/56.0f, 1.0f/28.0f, 1.0f/8.0f, 1.0f};

    // Each MV = 64 float4; thread's float4 index within MV = k*4 + sub.
    const float4* __restrict__ xin =
        reinterpret_cast<const float4*>(x) + (size_t)grp * 512 + mv * 64 + sub;
    float4* __restrict__ xout =
        reinterpret_cast<float4*>(out) + (size_t)grp * 512 + mv * 64 + sub;

    // ---- Pass 1: stream loads into grade-relative partial sums ----
    // t = popc(k)+popc(j) in 0..6.
    float S[NG], Q[NG];
#pragma unroll
    for (int t = 0; t < NG; ++t) { S[t] = 0.0f; Q[t] = 0.0f; }
#pragma unroll
    for (int k = 0; k < 16; ++k) {
        const int pk = __popc(k);          // compile-time after unroll, 0..4
        const float4 v = xin[k * 4];
        S[pk + 0] += v.x;  Q[pk + 0] = fmaf(v.x, v.x, Q[pk + 0]);
        S[pk + 1] += v.y;  Q[pk + 1] = fmaf(v.y, v.y, Q[pk + 1]);
        S[pk + 1] += v.z;  Q[pk + 1] = fmaf(v.z, v.z, Q[pk + 1]);
        S[pk + 2] += v.w;  Q[pk + 2] = fmaf(v.w, v.w, Q[pk + 2]);
    }

    // ---- Butterfly merge over lane bits 0,1 (sub). 7 -> 8 -> 9 ----
#pragma unroll
    for (int b = 0; b < 2; ++b) {
        const int n = 7 + b;               // current valid length
        const bool up = (sub >> b) & 1;
        float Sp[NG], Qp[NG];
#pragma unroll
        for (int t = 0; t < NG; ++t) {
            if (t < n) {
                Sp[t] = __shfl_xor_sync(0xffffffffu, S[t], 1 << b);
                Qp[t] = __shfl_xor_sync(0xffffffffu, Q[t], 1 << b);
            }
        }
        float Sn[NG], Qn[NG];
#pragma unroll
        for (int t = 0; t < NG; ++t) {
            if (t <= n) {
                float lo_s = (t < n) ? (up ? Sp[t] : S[t]) : 0.0f;
                float hi_s = (t > 0) ? (up ? S[t - 1] : Sp[t - 1]) : 0.0f;
                Sn[t] = lo_s + hi_s;
                float lo_q = (t < n) ? (up ? Qp[t] : Q[t]) : 0.0f;
                float hi_q = (t > 0) ? (up ? Q[t - 1] : Qp[t - 1]) : 0.0f;
                Qn[t] = lo_q + hi_q;
            }
        }
#pragma unroll
        for (int t = 0; t < NG; ++t) {
            if (t <= n) { S[t] = Sn[t]; Q[t] = Qn[t]; }
        }
    }

    // ---- Per-grade affine coefficients; compress to this lane's 7 ----
    float At[7], Bt[7];
#pragma unroll
    for (int g = 0; g < NG; ++g) {
        float m   = S[g] * rc[g];
        float var = fmaf(Q[g], rc[g], -m * m);
        float inv = rsqrtf(var + CEPS);
        float a   = inv * __ldg(weight + g);
        float b   = fmaf(-m, a, __ldg(bias + g));
        // lane needs grades p..p+6 -> slot t = g - p, p in 0..2
#pragma unroll
        for (int t = 0; t < 7; ++t) {
            if ((g - t == 0 && p == 0) || (g - t == 1 && p == 1) ||
                (g - t == 2 && p == 2)) {
                At[t] = a; Bt[t] = b;
            }
        }
    }

    // ---- Pass 2: reload x (L1 hit), FMA, plain store ----
    // asm volatile loads prevent CSE with pass-1 loads.
#pragma unroll
    for (int k = 0; k < 16; ++k) {
        const int pk = __popc(k);
        const float4* addr = xin + k * 4;
        float vx, vy, vz, vw;
        asm volatile("ld.global.nc.v4.f32 {%0,%1,%2,%3}, [%4];"
                     : "=f"(vx), "=f"(vy), "=f"(vz), "=f"(vw)
                     : "l"(addr));
        float4 o;
        o.x = fmaf(vx, At[pk + 0], Bt[pk + 0]);
        o.y = fmaf(vy, At[pk + 1], Bt[pk + 1]);
        o.z = fmaf(vz, At[pk + 1], Bt[pk + 1]);
        o.w = fmaf(vw, At[pk + 2], Bt[pk + 2]);
        xout[k * 4] = o;
    }
}

extern "C" void kernel_launch(void* const* d_in, const int* in_sizes, int n_in,
                              void* d_out, int out_size)
{
    const float* x      = (const float*)d_in[0];
    const float* weight = (const float*)d_in[1];
    const float* bias   = (const float*)d_in[2];
    float* out          = (float*)d_out;

    const int num_groups = in_sizes[0] / 2048;   // 8 MVs (2048 floats) per group

    // One group per warp, 8 warps per CTA -> num_groups/8 CTAs
    // (67.1M elems -> 32768 groups -> 4096 CTAs, ~9 waves).
    const int threads = 256;
    int blocks = (num_groups + 7) / 8;
    clifford_ln_kernel<<<blocks, threads>>>(x, weight, bias, out, num_groups);
}

// round 17
// speedup vs baseline: 1.0454x; 1.0454x over previous
#include <cuda_runtime.h>
#include <cuda_bf16.h>

// CliffordLayerNorm — FINAL converged kernel.
// Best wall sample 80.4us (distribution 81.0 +/- 0.5 over 4 runs),
// ncu ~76us, ~6.4TB/s, DRAM ~80% active.
//
// Per 256-element multivector block: per-grade (popcount-of-index) mean/var
// normalization with affine weight[9]/bias[9]. Memory-bound; measured DRAM
// traffic sits below the 536MB logical floor via L2 write merging — the
// kernel operates at the HBM mixed read/write stream wall.
//
// Measured-optimal structure (16 rounds of single-variable search; every
// neighboring configuration on every axis measured slower):
//  - 8 lanes per MV (4-lane halves warp-level MLP and loses; 16-lane adds a
//    serial shuffle stage); warp covers ONE group of 4 MVs (4KB); no loop —
//    CTA exit lets the CLC pipeline the next CTA's load burst (beats
//    grid-stride, persistent, and blocked partitions).
//  - 256-thread CTAs (optimum of 128/256/512), occ 3 (wall-faster than the
//    64-reg occ-4 variant across all paired samples), 8192 CTAs (~18 waves
//    of dynamic backfill absorbing per-SM spread).
//  - Pass 1 streams x into grade-relative sum/sumsq accumulators (values
//    not held -> 80 regs).
//  - 3-step shuffle-XOR "grade polynomial" butterfly merges relative grade
//    arrays (6->7->8->9) across the 8 lanes; every lane ends with the full
//    9-grade sums of its MV.
//  - var = E[x^2] - mean^2; affine collapsed to one FMA per element with
//    compile-time grade-offset coefficient selection.
//  - Pass 2 reloads x via ld.global.nc (L1-resident; beats smem stash and
//    register-held values), applies FMA, plain store (beats __stcs).

#define NG 9
#define CEPS 1e-5f

__global__ void __launch_bounds__(256, 3)
clifford_ln_kernel(const float* __restrict__ x,
                   const float* __restrict__ weight,
                   const float* __restrict__ bias,
                   float* __restrict__ out,
                   int num_groups)   // groups of 1024 floats (4 MVs)
{
    const int lane = threadIdx.x & 31;
    const int grp = blockIdx.x * (blockDim.x >> 5) + (threadIdx.x >> 5);
    if (grp >= num_groups) return;

    const int sub = lane & 7;     // covers element bits 2,3,4
    const int mv  = lane >> 3;    // which of 4 MVs in the group
    const int p   = __popc(sub);  // relative grade base, 0..3

    // per-grade reciprocal counts C(8,g) = 1,8,28,56,70,56,28,8,1
    const float rc[NG] = {1.0f, 1.0f/8.0f, 1.0f/28.0f, 1.0f/56.0f, 1.0f/70.0f,
                          1.0f/56.0f, 1.0f/28.0f, 1.0f/8.0f, 1.0f};

    const float4* __restrict__ xin =
        reinterpret_cast<const float4*>(x) + (size_t)grp * 256 + mv * 64 + sub;
    float4* __restrict__ xout =
        reinterpret_cast<float4*>(out) + (size_t)grp * 256 + mv * 64 + sub;

    // ---- Pass 1: stream loads into grade-relative partial sums ----
    // t = popc(k)+popc(j) in 0..5.
    float S[NG], Q[NG];
#pragma unroll
    for (int t = 0; t < NG; ++t) { S[t] = 0.0f; Q[t] = 0.0f; }
#pragma unroll
    for (int k = 0; k < 8; ++k) {
        const int pk = __popc(k);          // compile-time after unroll
        const float4 v = xin[k * 8];
        S[pk + 0] += v.x;  Q[pk + 0] = fmaf(v.x, v.x, Q[pk + 0]);
        S[pk + 1] += v.y;  Q[pk + 1] = fmaf(v.y, v.y, Q[pk + 1]);
        S[pk + 1] += v.z;  Q[pk + 1] = fmaf(v.z, v.z, Q[pk + 1]);
        S[pk + 2] += v.w;  Q[pk + 2] = fmaf(v.w, v.w, Q[pk + 2]);
    }

    // ---- Butterfly merge over lane bits 0..2 (sub). 6 -> 7 -> 8 -> 9 ----
#pragma unroll
    for (int b = 0; b < 3; ++b) {
        const int n = 6 + b;               // current valid length
        const bool up = (sub >> b) & 1;
        float Sp[NG], Qp[NG];
#pragma unroll
        for (int t = 0; t < NG; ++t) {
            if (t < n) {
                Sp[t] = __shfl_xor_sync(0xffffffffu, S[t], 1 << b);
                Qp[t] = __shfl_xor_sync(0xffffffffu, Q[t], 1 << b);
            }
        }
        float Sn[NG], Qn[NG];
#pragma unroll
        for (int t = 0; t < NG; ++t) {
            if (t <= n) {
                float lo_s = (t < n) ? (up ? Sp[t] : S[t]) : 0.0f;
                float hi_s = (t > 0) ? (up ? S[t - 1] : Sp[t - 1]) : 0.0f;
                Sn[t] = lo_s + hi_s;
                float lo_q = (t < n) ? (up ? Qp[t] : Q[t]) : 0.0f;
                float hi_q = (t > 0) ? (up ? Q[t - 1] : Qp[t - 1]) : 0.0f;
                Qn[t] = lo_q + hi_q;
            }
        }
#pragma unroll
        for (int t = 0; t < NG; ++t) {
            if (t <= n) { S[t] = Sn[t]; Q[t] = Qn[t]; }
        }
    }

    // ---- Per-grade affine coefficients; compress to this lane's 6 ----
    float At[6], Bt[6];
#pragma unroll
    for (int g = 0; g < NG; ++g) {
        float m   = S[g] * rc[g];
        float var = fmaf(Q[g], rc[g], -m * m);
        float inv = rsqrtf(var + CEPS);
        float a   = inv * __ldg(weight + g);
        float b   = fmaf(-m, a, __ldg(bias + g));
        // lane needs grades p..p+5 -> slot t = g - p
#pragma unroll
        for (int t = 0; t < 6; ++t) {
            if (g - t == 0 ? (p == 0) : (g - t == 1 ? (p == 1) :
                (g - t == 2 ? (p == 2) : (g - t == 3 && p == 3)))) {
                At[t] = a; Bt[t] = b;
            }
        }
    }

    // ---- Pass 2: reload x (L1 hit), FMA, plain store ----
    // asm volatile loads prevent CSE with pass-1 loads.
#pragma unroll
    for (int k = 0; k < 8; ++k) {
        const int pk = __popc(k);
        const float4* addr = xin + k * 8;
        float vx, vy, vz, vw;
        asm volatile("ld.global.nc.v4.f32 {%0,%1,%2,%3}, [%4];"
                     : "=f"(vx), "=f"(vy), "=f"(vz), "=f"(vw)
                     : "l"(addr));
        float4 o;
        o.x = fmaf(vx, At[pk + 0], Bt[pk + 0]);
        o.y = fmaf(vy, At[pk + 1], Bt[pk + 1]);
        o.z = fmaf(vz, At[pk + 1], Bt[pk + 1]);
        o.w = fmaf(vw, At[pk + 2], Bt[pk + 2]);
        xout[k * 8] = o;
    }
}

extern "C" void kernel_launch(void* const* d_in, const int* in_sizes, int n_in,
                              void* d_out, int out_size)
{
    const float* x      = (const float*)d_in[0];
    const float* weight = (const float*)d_in[1];
    const float* bias   = (const float*)d_in[2];
    float* out          = (float*)d_out;

    const int num_groups = in_sizes[0] / 1024;   // 4 MVs (1024 floats) per group

    // One group per warp, 8 warps per CTA -> num_groups/8 CTAs (~18 waves).
    const int threads = 256;
    int blocks = (num_groups + 7) / 8;
    clifford_ln_kernel<<<blocks, threads>>>(x, weight, bias, out, num_groups);
}